// round 8
// baseline (speedup 1.0000x reference)
#include <cuda_runtime.h>
#include <cstdint>
#include <cstddef>

#define TT 512
#define CC 128
#define LL 80
#define BLANKC 127
#define FEPS 1e-7f
#define FULLM 0xffffffffu
#define RING 48
#define NGRP 5          // commit groups in flight
#define PRIME (8 * NGRP)

__device__ __forceinline__ void cp_async16(void* smem, const void* gmem) {
    unsigned s = (unsigned)__cvta_generic_to_shared(smem);
    asm volatile("cp.async.ca.shared.global [%0], [%1], 16;\n" :: "r"(s), "l"(gmem));
}
__device__ __forceinline__ void cp_commit() {
    asm volatile("cp.async.commit_group;\n" ::: "memory");
}
__device__ __forceinline__ void cp_waitg() {
    asm volatile("cp.async.wait_group %0;\n" :: "n"(NGRP - 1) : "memory");
}

// 128 blocks x 128 threads: one warp per SMSP, one batch element per warp.
// Streaming: per-warp 48-row smem ring, cp.async in 8-row commit groups,
// wait_group 4 (5 groups / 20KB per warp in flight). ALL per-row reads
// (3 label gathers, blank, norm float4) come from the smem ring via LDS and
// are PREFETCHED ONE STEP AHEAD into registers, so LDS latency+conflict
// replays are off the loop-carried path (which is now just the shfl+fma
// recursion chain, ~40cyc). Row log-norms via a 5-stage software-pipelined
// shfl butterfly. States split by parity:
//  e_i = alpha[2i]   (blank, i=0..80): lane l holds e_l, e_{32+l}, e_{64+l}
//  o_i = alpha[2i+1] (label, i=0..79): lane l holds o_l, o_{32+l}, o_{64+l}
// Linear-domain recursion with 8-step lagged rescaling; float accumulators.
__global__ void __launch_bounds__(128, 1) ctc_kernel(
    const int* __restrict__ lab32,
    const float* __restrict__ ypred,
    float* __restrict__ out)
{
    extern __shared__ __align__(16) float ring[];   // [4][RING][CC] = 96 KB
    const int lane = threadIdx.x & 31;
    const int w = threadIdx.x >> 5;
    const int b = blockIdx.x * 4 + w;
    float* __restrict__ rw = ring + (size_t)w * RING * CC;
    const float* __restrict__ yb = ypred + (size_t)b * (TT * CC);

    // detect label element width (int64 little-endian vs int32)
    int probe = lab32[1] | lab32[3] | lab32[5] | lab32[7]
              | lab32[9] | lab32[11] | lab32[13] | lab32[15];
    const int stride = (probe == 0) ? 2 : 1;
    const int* lb = lab32 + (size_t)b * LL * stride;

    const int i1 = 32 + lane, i2 = 64 + lane;
    const int L0 = lb[lane * stride];
    const int L1 = lb[i1 * stride];
    const bool v2 = (i2 < LL);
    const int L2 = v2 ? lb[i2 * stride] : BLANKC;
    const float al0 = (lane == 0) ? 0.f : ((L0 != lb[(lane - 1) * stride]) ? 1.f : 0.f);
    const float al1 = (L1 != lb[(i1 - 1) * stride]) ? 1.f : 0.f;
    const float al2 = (v2 && (L2 != lb[(i2 - 1) * stride])) ? 1.f : 0.f;

    // prime NGRP groups: rows 0..PRIME-1
#pragma unroll
    for (int g = 0; g < NGRP; g++) {
#pragma unroll
        for (int r = 0; r < 8; r++) {
            int row = g * 8 + r;
            cp_async16(rw + row * CC + lane * 4, yb + (size_t)row * CC + lane * 4);
        }
        cp_commit();
    }

    float e0 = 0.f, e1 = 0.f, e2 = 0.f, o0 = 0.f, o1 = 0.f, o2 = 0.f;
    float np0 = 0.f, np1 = 0.f, np2 = 0.f, np3 = 0.f, np4 = 0.f;
    float accN0 = 0.f, accN1 = 0.f, accS = 0.f;
    float rs = 0.f, pend = 0.f, cN = 1.f;
    float4 pf4 = make_float4(0.f, 0.f, 0.f, 0.f);
    float pfB = 0.f, pf0 = 0.f, pf1 = 0.f, pf2 = 0.f;
    const float* rp = rw;                 // smem pointer for row t
    const float* const rlast = rw + (RING - 1) * CC;
    int t = 0;

#define CTC_STEP(FIRST, U) do {                                                     \
    float yB, y0r, y1r, y2r; float4 v4;                                             \
    if ((U) == 0) {                                                                 \
        cp_waitg();                                                                 \
        __syncwarp();                                                               \
        _Pragma("unroll")                                                           \
        for (int j = 0; j < 8; j++) {                                               \
            int tn = t + PRIME + j;                                                 \
            if (tn < TT)                                                            \
                cp_async16(rw + ((tn % RING) * CC) + lane * 4,                      \
                           yb + (size_t)tn * CC + lane * 4);                        \
        }                                                                           \
        cp_commit();                                                                \
        v4 = *(const float4*)(rp + lane * 4);                                       \
        yB = rp[BLANKC]; y0r = rp[L0]; y1r = rp[L1]; y2r = rp[L2];                  \
    } else {                                                                        \
        v4 = pf4; yB = pfB; y0r = pf0; y1r = pf1; y2r = pf2;                        \
    }                                                                               \
    const float* rn = (rp == rlast) ? rw : rp + CC;                                 \
    if ((U) < 7) {                                                                  \
        pf4 = *(const float4*)(rn + lane * 4);                                      \
        pfB = rn[BLANKC]; pf0 = rn[L0]; pf1 = rn[L1]; pf2 = rn[L2];                 \
    }                                                                               \
    float loc = (v4.x + v4.y) + (v4.z + v4.w);                                      \
    yB += FEPS;                                                                     \
    float y0 = y0r + FEPS;                                                          \
    float y1 = y1r + FEPS;                                                          \
    float y2 = v2 ? (y2r + FEPS) : 0.f;                                             \
    /* norm pipeline: finish row t-5 */                                             \
    if (!(FIRST) || (U) >= 5) {                                                     \
        float fin = np4 + __shfl_xor_sync(FULLM, np4, 1);                           \
        float lg = __logf(fin + (float)CC * FEPS);                                  \
        if (((U) & 1) == 0) accN0 += lg; else accN1 += lg;                          \
    }                                                                               \
    np4 = np3 + __shfl_xor_sync(FULLM, np3, 2);                                     \
    np3 = np2 + __shfl_xor_sync(FULLM, np2, 4);                                     \
    np2 = np1 + __shfl_xor_sync(FULLM, np1, 8);                                     \
    np1 = np0 + __shfl_xor_sync(FULLM, np0, 16);                                    \
    np0 = loc;                                                                      \
    if ((FIRST) && (U) == 0) {                                                      \
        e0 = (lane == 0) ? yB : 0.f;                                                \
        o0 = (lane == 0) ? y0 : 0.f;                                                \
    } else {                                                                        \
        float bb0 = __shfl_sync(FULLM, o0, 31);                                     \
        float bb1 = __shfl_sync(FULLM, o1, 31);                                     \
        float m0 = __shfl_up_sync(FULLM, o0, 1);                                    \
        float m1 = __shfl_up_sync(FULLM, o1, 1);                                    \
        float m2 = __shfl_up_sync(FULLM, o2, 1);                                    \
        if (lane == 0) { m0 = 0.f; m1 = bb0; m2 = bb1; }                            \
        float ne0 = yB * (e0 + m0);                                                 \
        float ne1 = yB * (e1 + m1);                                                 \
        float ne2 = yB * (e2 + m2);                                                 \
        float no0 = y0 * __fmaf_rn(al0, m0, o0 + e0);                               \
        float no1 = y1 * __fmaf_rn(al1, m1, o1 + e1);                               \
        float no2 = y2 * __fmaf_rn(al2, m2, o2 + e2);                               \
        e0 = ne0; e1 = ne1; e2 = ne2; o0 = no0; o1 = no1; o2 = no2;                 \
    }                                                                               \
    /* lagged rescale: one butterfly stage per step, applied at U==7 */             \
    if ((U) == 0)      { rs = ((e0 + e1) + (e2 + o0)) + (o1 + o2); }                \
    else if ((U) == 1) { rs += __shfl_xor_sync(FULLM, rs, 16); }                    \
    else if ((U) == 2) { rs += __shfl_xor_sync(FULLM, rs, 8); }                     \
    else if ((U) == 3) { rs += __shfl_xor_sync(FULLM, rs, 4); }                     \
    else if ((U) == 4) { rs += __shfl_xor_sync(FULLM, rs, 2); }                     \
    else if ((U) == 5) { rs += __shfl_xor_sync(FULLM, rs, 1); }                     \
    else if ((U) == 6) { pend = __logf(rs); cN = __fdividef(1.f, rs); }             \
    else               { e0 *= cN; e1 *= cN; e2 *= cN;                              \
                         o0 *= cN; o1 *= cN; o2 *= cN; accS += pend; }              \
    rp = rn;                                                                        \
    t++;                                                                            \
} while (0)

    CTC_STEP(1, 0); CTC_STEP(1, 1); CTC_STEP(1, 2); CTC_STEP(1, 3);
    CTC_STEP(1, 4); CTC_STEP(1, 5); CTC_STEP(1, 6); CTC_STEP(1, 7);

#pragma unroll 1
    for (int g = 1; g < TT / 8; g++) {
        CTC_STEP(0, 0); CTC_STEP(0, 1); CTC_STEP(0, 2); CTC_STEP(0, 3);
        CTC_STEP(0, 4); CTC_STEP(0, 5); CTC_STEP(0, 6); CTC_STEP(0, 7);
    }
#undef CTC_STEP

    // drain norm pipeline (rows TT-5 .. TT-1)
#pragma unroll
    for (int d = 0; d < 5; d++) {
        float fin = np4 + __shfl_xor_sync(FULLM, np4, 1);
        float lg = __logf(fin + (float)CC * FEPS);
        if ((d & 1) == 0) accN0 += lg; else accN1 += lg;
        np4 = np3 + __shfl_xor_sync(FULLM, np3, 2);
        np3 = np2 + __shfl_xor_sync(FULLM, np2, 4);
        np2 = np1 + __shfl_xor_sync(FULLM, np1, 8);
        np1 = np0 + __shfl_xor_sync(FULLM, np0, 16);
        np0 = 0.f;
    }

    // tail: states 160 (e_80 = e2@lane16) and 159 (o_79 = o2@lane15)
    float accN = accN0 + accN1;
    float e80 = __shfl_sync(FULLM, e2, 16);
    float o79 = __shfl_sync(FULLM, o2, 15);
    if (lane == 0) {
        out[b] = -(__logf(e80 + o79) + accS - accN);
    }
}

extern "C" void kernel_launch(void* const* d_in, const int* in_sizes, int n_in,
                              void* d_out, int out_size) {
    (void)in_sizes; (void)n_in; (void)out_size;
    const int* labels = (const int*)d_in[0];
    const float* ypred = (const float*)d_in[1];
    float* out = (float*)d_out;
    const int smem = 4 * RING * CC * (int)sizeof(float);   // 96 KB
    cudaFuncSetAttribute(ctc_kernel, cudaFuncAttributeMaxDynamicSharedMemorySize, smem);
    ctc_kernel<<<128, 128, smem>>>(labels, ypred, out);
}

// round 13
// speedup vs baseline: 1.1484x; 1.1484x over previous
#include <cuda_runtime.h>
#include <cstdint>
#include <cstddef>

#define TT 512
#define CC 128
#define LL 80
#define BLANKC 127
#define FEPS 1e-7f
#define FULLM 0xffffffffu
#define RING 32
#define NGRP 3
#define PRIME 24

__device__ __forceinline__ void cp_async16(void* smem, const void* gmem) {
    unsigned s = (unsigned)__cvta_generic_to_shared(smem);
    asm volatile("cp.async.ca.shared.global [%0], [%1], 16;\n" :: "r"(s), "l"(gmem));
}
__device__ __forceinline__ void cp_commit() {
    asm volatile("cp.async.commit_group;\n" ::: "memory");
}
__device__ __forceinline__ void cp_waitg() {
    asm volatile("cp.async.wait_group %0;\n" :: "n"(NGRP - 1) : "memory");
}

// 128 blocks x 128 threads: one warp per SMSP, one batch element per warp.
// R6-proven architecture (32-row smem ring, cp.async 8-row commit groups,
// 3 groups in flight, all row reads via LDS, linear-domain recursion with
// 8-step lagged rescaling, 5-stage pipelined norm butterfly), plus:
//  (a) the 4 gather scalars (blank + 3 label columns) for step k+1 are
//      prefetched into registers during step k (U<7 only — same waited
//      group), taking LDS latency + conflict replays off the loop-carried
//      recursion path;
//  (b) the recursion's 5 shfls collapse to 3 shfl.idx with wraparound
//      (lane-1 mod 32) + 3 selects — lane 0 of the rotation IS the lane-31
//      broadcast the old code fetched separately. Bit-identical results.
// States split by parity: e_i = alpha[2i] (blank, i=0..80) at lane i%32 reg
// i/32; o_i = alpha[2i+1] (label, i=0..79) likewise.
__global__ void __launch_bounds__(128, 1) ctc_kernel(
    const int* __restrict__ lab32,
    const float* __restrict__ ypred,
    float* __restrict__ out)
{
    extern __shared__ __align__(16) float ring[];   // [4][RING][CC] = 64 KB
    const int lane = threadIdx.x & 31;
    const int w = threadIdx.x >> 5;
    const int b = blockIdx.x * 4 + w;
    const int lanem1 = (lane + 31) & 31;
    float* __restrict__ rw = ring + (size_t)w * RING * CC;
    const float* __restrict__ yb = ypred + (size_t)b * (TT * CC);

    // detect label element width (int64 little-endian vs int32)
    int probe = lab32[1] | lab32[3] | lab32[5] | lab32[7]
              | lab32[9] | lab32[11] | lab32[13] | lab32[15];
    const int stride = (probe == 0) ? 2 : 1;
    const int* lb = lab32 + (size_t)b * LL * stride;

    const int i1 = 32 + lane, i2 = 64 + lane;
    const int L0 = lb[lane * stride];
    const int L1 = lb[i1 * stride];
    const bool v2 = (i2 < LL);
    const int L2 = v2 ? lb[i2 * stride] : BLANKC;
    const float al0 = (lane == 0) ? 0.f : ((L0 != lb[(lane - 1) * stride]) ? 1.f : 0.f);
    const float al1 = (L1 != lb[(i1 - 1) * stride]) ? 1.f : 0.f;
    const float al2 = (v2 && (L2 != lb[(i2 - 1) * stride])) ? 1.f : 0.f;

    // prime NGRP groups: rows 0..PRIME-1
#pragma unroll
    for (int g = 0; g < NGRP; g++) {
#pragma unroll
        for (int r = 0; r < 8; r++) {
            int row = g * 8 + r;
            cp_async16(rw + row * CC + lane * 4, yb + (size_t)row * CC + lane * 4);
        }
        cp_commit();
    }

    float e0 = 0.f, e1 = 0.f, e2 = 0.f, o0 = 0.f, o1 = 0.f, o2 = 0.f;
    float np0 = 0.f, np1 = 0.f, np2 = 0.f, np3 = 0.f, np4 = 0.f;
    float accN0 = 0.f, accN1 = 0.f, accS = 0.f;
    float rs = 0.f, pend = 0.f, cN = 1.f;
    float pB = 0.f, p0 = 0.f, p1 = 0.f, p2 = 0.f;   // gather prefetch regs
    int t = 0;

#define CTC_STEP(FIRST, U) do {                                                     \
    float yB, y0, y1, y2;                                                           \
    if ((U) == 0) {                                                                 \
        cp_waitg();                                                                 \
        __syncwarp();                                                               \
        _Pragma("unroll")                                                           \
        for (int j = 0; j < 8; j++) {                                               \
            int tn = t + PRIME + j;                                                 \
            if (tn < TT)                                                            \
                cp_async16(rw + ((tn & (RING - 1)) * CC) + lane * 4,                \
                           yb + (size_t)tn * CC + lane * 4);                        \
        }                                                                           \
        cp_commit();                                                                \
        const float* rg = rw + ((t & (RING - 1)) * CC);                             \
        yB = rg[BLANKC] + FEPS;                                                     \
        y0 = rg[L0] + FEPS;                                                         \
        y1 = rg[L1] + FEPS;                                                         \
        y2 = v2 ? (rg[L2] + FEPS) : 0.f;                                            \
    } else {                                                                        \
        yB = pB + FEPS;                                                             \
        y0 = p0 + FEPS;                                                             \
        y1 = p1 + FEPS;                                                             \
        y2 = v2 ? (p2 + FEPS) : 0.f;                                                \
    }                                                                               \
    if ((U) < 7) {                                                                  \
        const float* rn = rw + (((t + 1) & (RING - 1)) * CC);                       \
        pB = rn[BLANKC]; p0 = rn[L0]; p1 = rn[L1]; p2 = rn[L2];                     \
    }                                                                               \
    const float* rp = rw + ((t & (RING - 1)) * CC);                                 \
    float4 v4 = *(const float4*)(rp + lane * 4);                                    \
    float loc = (v4.x + v4.y) + (v4.z + v4.w);                                      \
    /* norm pipeline: finish row t-5 */                                             \
    if (!(FIRST) || (U) >= 5) {                                                     \
        float fin = np4 + __shfl_xor_sync(FULLM, np4, 1);                           \
        float lg = __logf(fin + (float)CC * FEPS);                                  \
        if (((U) & 1) == 0) accN0 += lg; else accN1 += lg;                          \
    }                                                                               \
    np4 = np3 + __shfl_xor_sync(FULLM, np3, 2);                                     \
    np3 = np2 + __shfl_xor_sync(FULLM, np2, 4);                                     \
    np2 = np1 + __shfl_xor_sync(FULLM, np1, 8);                                     \
    np1 = np0 + __shfl_xor_sync(FULLM, np0, 16);                                    \
    np0 = loc;                                                                      \
    if ((FIRST) && (U) == 0) {                                                      \
        e0 = (lane == 0) ? yB : 0.f;                                                \
        o0 = (lane == 0) ? y0 : 0.f;                                                \
    } else {                                                                        \
        /* rotate-by-1 with wraparound: lane l gets o@(l-1 mod 32);                 \
           lane 0 receives lane 31's value = the old bb broadcasts */               \
        float r0 = __shfl_sync(FULLM, o0, lanem1);                                  \
        float r1 = __shfl_sync(FULLM, o1, lanem1);                                  \
        float r2 = __shfl_sync(FULLM, o2, lanem1);                                  \
        float m0 = (lane == 0) ? 0.f : r0;                                          \
        float m1 = (lane == 0) ? r0 : r1;                                           \
        float m2 = (lane == 0) ? r1 : r2;                                           \
        float ne0 = yB * (e0 + m0);                                                 \
        float ne1 = yB * (e1 + m1);                                                 \
        float ne2 = yB * (e2 + m2);                                                 \
        float no0 = y0 * __fmaf_rn(al0, m0, o0 + e0);                               \
        float no1 = y1 * __fmaf_rn(al1, m1, o1 + e1);                               \
        float no2 = y2 * __fmaf_rn(al2, m2, o2 + e2);                               \
        e0 = ne0; e1 = ne1; e2 = ne2; o0 = no0; o1 = no1; o2 = no2;                 \
    }                                                                               \
    /* lagged rescale: one butterfly stage per step, applied at U==7 */             \
    if ((U) == 0)      { rs = ((e0 + e1) + (e2 + o0)) + (o1 + o2); }                \
    else if ((U) == 1) { rs += __shfl_xor_sync(FULLM, rs, 16); }                    \
    else if ((U) == 2) { rs += __shfl_xor_sync(FULLM, rs, 8); }                     \
    else if ((U) == 3) { rs += __shfl_xor_sync(FULLM, rs, 4); }                     \
    else if ((U) == 4) { rs += __shfl_xor_sync(FULLM, rs, 2); }                     \
    else if ((U) == 5) { rs += __shfl_xor_sync(FULLM, rs, 1); }                     \
    else if ((U) == 6) { pend = __logf(rs); cN = __fdividef(1.f, rs); }             \
    else               { e0 *= cN; e1 *= cN; e2 *= cN;                              \
                         o0 *= cN; o1 *= cN; o2 *= cN; accS += pend; }              \
    t++;                                                                            \
} while (0)

    CTC_STEP(1, 0); CTC_STEP(1, 1); CTC_STEP(1, 2); CTC_STEP(1, 3);
    CTC_STEP(1, 4); CTC_STEP(1, 5); CTC_STEP(1, 6); CTC_STEP(1, 7);

#pragma unroll 1
    for (int g = 1; g < TT / 8; g++) {
        CTC_STEP(0, 0); CTC_STEP(0, 1); CTC_STEP(0, 2); CTC_STEP(0, 3);
        CTC_STEP(0, 4); CTC_STEP(0, 5); CTC_STEP(0, 6); CTC_STEP(0, 7);
    }
#undef CTC_STEP

    // drain norm pipeline (rows TT-5 .. TT-1)
#pragma unroll
    for (int d = 0; d < 5; d++) {
        float fin = np4 + __shfl_xor_sync(FULLM, np4, 1);
        float lg = __logf(fin + (float)CC * FEPS);
        if ((d & 1) == 0) accN0 += lg; else accN1 += lg;
        np4 = np3 + __shfl_xor_sync(FULLM, np3, 2);
        np3 = np2 + __shfl_xor_sync(FULLM, np2, 4);
        np2 = np1 + __shfl_xor_sync(FULLM, np1, 8);
        np1 = np0 + __shfl_xor_sync(FULLM, np0, 16);
        np0 = 0.f;
    }

    // tail: states 160 (e_80 = e2@lane16) and 159 (o_79 = o2@lane15)
    float accN = accN0 + accN1;
    float e80 = __shfl_sync(FULLM, e2, 16);
    float o79 = __shfl_sync(FULLM, o2, 15);
    if (lane == 0) {
        out[b] = -(__logf(e80 + o79) + accS - accN);
    }
}

extern "C" void kernel_launch(void* const* d_in, const int* in_sizes, int n_in,
                              void* d_out, int out_size) {
    (void)in_sizes; (void)n_in; (void)out_size;
    const int* labels = (const int*)d_in[0];
    const float* ypred = (const float*)d_in[1];
    float* out = (float*)d_out;
    const int smem = 4 * RING * CC * (int)sizeof(float);   // 64 KB
    cudaFuncSetAttribute(ctc_kernel, cudaFuncAttributeMaxDynamicSharedMemorySize, smem);
    ctc_kernel<<<128, 128, smem>>>(labels, ypred, out);
}